// round 14
// baseline (speedup 1.0000x reference)
#include <cuda_runtime.h>
#include <cuda_bf16.h>
#include <math.h>
#include <stdint.h>

#define N_TOK 1024
#define C_IN  512
#define CQ    64
#define BATCH 32

#if defined(__CUDA_ARCH__)
#if defined(__CUDA_ARCH_FEAT_SM103_ALL)
#define USE_TCGEN05 1
#else
#define USE_TCGEN05 0
#endif
#else
#define USE_TCGEN05 0
#endif

// ---------------- scratch (device globals; no allocation allowed) ----------
__device__ __align__(128) __nv_bfloat16 g_Wn_hi[640 * C_IN];   // rows: q 0-63, k 64-127, v 128-639 (K-major)
__device__ __align__(128) __nv_bfloat16 g_Wn_lo[640 * C_IN];
__device__ __align__(128) float g_bias[640];
__device__ __align__(128) __nv_bfloat16 g_xT_hi[(size_t)BATCH * N_TOK * C_IN];  // [b][n][c]
__device__ __align__(128) __nv_bfloat16 g_xT_lo[(size_t)BATCH * N_TOK * C_IN];
__device__ __align__(128) __nv_bfloat16 g_qT_hi[(size_t)BATCH * N_TOK * CQ];    // [b][n][o]
__device__ __align__(128) __nv_bfloat16 g_qT_lo[(size_t)BATCH * N_TOK * CQ];
__device__ __align__(128) __nv_bfloat16 g_kT_hi[(size_t)BATCH * N_TOK * CQ];    // [b][m][o]
__device__ __align__(128) __nv_bfloat16 g_kT_lo[(size_t)BATCH * N_TOK * CQ];
__device__ __align__(128) __nv_bfloat16 g_v_hi [(size_t)BATCH * C_IN * N_TOK];  // [b][c][n]
__device__ __align__(128) __nv_bfloat16 g_v_lo [(size_t)BATCH * C_IN * N_TOK];
__device__ __align__(128) __nv_bfloat16 g_P    [(size_t)BATCH * N_TOK * N_TOK]; // [b][m][n] unnormalized exp(S), bf16
__device__ __align__(128) float         g_rsum [(size_t)BATCH * N_TOK];         // [b][m] row sums

// ---------------- common helpers --------------------------------------------
__device__ __forceinline__ uint32_t cvta_smem(const void* p) {
    uint32_t a;
    asm("{ .reg .u64 t; cvta.to.shared.u64 t, %1; cvt.u32.u64 %0, t; }" : "=r"(a) : "l"(p));
    return a;
}
__device__ __forceinline__ void pack_split2(float a, float b, uint32_t& h, uint32_t& l) {
    __nv_bfloat16 ah = __float2bfloat16(a);
    __nv_bfloat16 bh = __float2bfloat16(b);
    __nv_bfloat16 al = __float2bfloat16(a - __bfloat162float(ah));
    __nv_bfloat16 bl = __float2bfloat16(b - __bfloat162float(bh));
    h = (uint32_t)__bfloat16_as_ushort(ah) | ((uint32_t)__bfloat16_as_ushort(bh) << 16);
    l = (uint32_t)__bfloat16_as_ushort(al) | ((uint32_t)__bfloat16_as_ushort(bl) << 16);
}
__device__ __forceinline__ uint32_t pack_bf2(float a, float b) {
    return (uint32_t)__bfloat16_as_ushort(__float2bfloat16(a)) |
           ((uint32_t)__bfloat16_as_ushort(__float2bfloat16(b)) << 16);
}
__device__ __forceinline__ void split1(float v, __nv_bfloat16& h, __nv_bfloat16& l) {
    h = __float2bfloat16(v);
    l = __float2bfloat16(v - __bfloat162float(h));
}

#if USE_TCGEN05
__device__ __forceinline__ int elect_one() {
    uint32_t pred;
    asm volatile("{\n\t.reg .pred p;\n\telect.sync _|p, 0xFFFFFFFF;\n\tselp.b32 %0, 1, 0, p;\n\t}" : "=r"(pred));
    return (int)pred;
}
#define MB_INIT(addr, cnt) \
    asm volatile("mbarrier.init.shared.b64 [%0], %1;" :: "r"(addr), "r"((uint32_t)(cnt)) : "memory")
#define MB_WAIT(addr, phv) do { \
    uint32_t _m = (addr), _p = (uint32_t)(phv), _d; \
    asm volatile("{\n\t.reg .pred p;\n\t" \
        "mbarrier.try_wait.parity.acquire.cta.shared::cta.b64 p, [%1], %2;\n\t" \
        "selp.b32 %0,1,0,p;\n\t}" : "=r"(_d) : "r"(_m), "r"(_p) : "memory"); \
    while (!_d) { \
        asm volatile("{\n\t.reg .pred p;\n\t" \
            "mbarrier.try_wait.parity.acquire.cta.shared::cta.b64 p, [%1], %2, 0x989680;\n\t" \
            "selp.b32 %0,1,0,p;\n\t}" : "=r"(_d) : "r"(_m), "r"(_p) : "memory"); \
    } \
} while (0)
#define TC_ALLOC(addr, n) \
    asm volatile("tcgen05.alloc.cta_group::1.sync.aligned.shared::cta.b32 [%0], %1;" :: "r"(addr), "r"((uint32_t)(n)) : "memory")
#define TC_RELINQ() \
    asm volatile("tcgen05.relinquish_alloc_permit.cta_group::1.sync.aligned;")
#define TC_DEALLOC(tm, n) \
    asm volatile("tcgen05.dealloc.cta_group::1.sync.aligned.b32 %0, %1;" :: "r"(tm), "r"((uint32_t)(n)))
#define TC_COMMIT(addr) \
    asm volatile("tcgen05.commit.cta_group::1.mbarrier::arrive::one.shared::cluster.b64 [%0];" :: "r"(addr) : "memory")
#define TC_FENCE_AFTER()   asm volatile("tcgen05.fence::after_thread_sync;" ::: "memory")
#define TC_FENCE_BEFORE()  asm volatile("tcgen05.fence::before_thread_sync;" ::: "memory")
#define TC_WAIT_LD()       asm volatile("tcgen05.wait::ld.sync.aligned;" ::: "memory")
#define FENCE_ASYNC()      asm volatile("fence.proxy.async.shared::cta;" ::: "memory")
#define CP16(dst, src)  asm volatile("cp.async.cg.shared.global [%0], [%1], 16;" :: "r"(dst), "l"(src) : "memory")
#define CP_COMMIT()     asm volatile("cp.async.commit_group;" ::: "memory")
#define CP_WAIT0()      asm volatile("cp.async.wait_group 0;" ::: "memory")

#define LDTM32(r, tma) \
    asm volatile("tcgen05.ld.sync.aligned.32x32b.x32.b32 " \
        "{%0,%1,%2,%3,%4,%5,%6,%7,%8,%9,%10,%11,%12,%13,%14,%15," \
        "%16,%17,%18,%19,%20,%21,%22,%23,%24,%25,%26,%27,%28,%29,%30,%31}, [%32];" \
        : "=r"((r)[0]),"=r"((r)[1]),"=r"((r)[2]),"=r"((r)[3]),"=r"((r)[4]),"=r"((r)[5]),"=r"((r)[6]),"=r"((r)[7]), \
          "=r"((r)[8]),"=r"((r)[9]),"=r"((r)[10]),"=r"((r)[11]),"=r"((r)[12]),"=r"((r)[13]),"=r"((r)[14]),"=r"((r)[15]), \
          "=r"((r)[16]),"=r"((r)[17]),"=r"((r)[18]),"=r"((r)[19]),"=r"((r)[20]),"=r"((r)[21]),"=r"((r)[22]),"=r"((r)[23]), \
          "=r"((r)[24]),"=r"((r)[25]),"=r"((r)[26]),"=r"((r)[27]),"=r"((r)[28]),"=r"((r)[29]),"=r"((r)[30]),"=r"((r)[31]) \
        : "r"(tma))

// SW128 desc (128B rows): layout 2, version 1, SBO=64, LBO=1
__device__ __forceinline__ uint64_t smem_desc(uint32_t addr) {
    return 0x4000404000010000ULL | (uint64_t)((addr >> 4) & 0x3FFF);
}
// SW64 desc (64B rows): layout 4, version 1, SBO=32, LBO=1
__device__ __forceinline__ uint64_t smem_desc64(uint32_t addr) {
    return 0x8000402000010000ULL | (uint64_t)((addr >> 4) & 0x3FFF);
}
__device__ __forceinline__ void mma_bf16_ss(uint32_t d, uint64_t ad, uint64_t bd,
                                            uint32_t idesc, uint32_t en) {
    asm volatile(
        "{\n\t.reg .pred p;\n\tsetp.ne.u32 p, %4, 0;\n\t"
        "tcgen05.mma.cta_group::1.kind::f16 [%0], %1, %2, %3, {%5,%5,%5,%5}, p;\n\t}"
        :: "r"(d), "l"(ad), "l"(bd), "r"(idesc), "r"(en), "r"(0u) : "memory");
}
#define IDESC(NN) (0x8000490u | ((uint32_t)((NN) / 8) << 17))

// ---- SW128 (128B rows, K-chunk 64) copy ----
__device__ __forceinline__ void copy_rows(const __nv_bfloat16* __restrict__ src,
                                          int stride, int k0, uint32_t dst,
                                          int rows, int tid) {
    for (int s = tid; s < rows * 8; s += 256) {
        int r = s >> 3, seg = s & 7;
        const char* sp = (const char*)(src + (size_t)r * stride + k0) + seg * 16;
        uint32_t off = (uint32_t)(r * 128 + seg * 16);
        uint32_t sw = off ^ ((off >> 3) & 0x70u);
        CP16(dst + sw, sp);
    }
}
// ---- SW64 (64B rows, K-chunk 32) copy ----
__device__ __forceinline__ void copy_rows64(const __nv_bfloat16* __restrict__ src,
                                            int stride, int k0, uint32_t dst,
                                            int rows, int tid) {
    for (int s = tid; s < rows * 4; s += 256) {
        int r = s >> 2, seg = s & 3;
        const char* sp = (const char*)(src + (size_t)r * stride + k0) + seg * 16;
        uint32_t off = (uint32_t)(r * 64 + seg * 16);
        uint32_t sw = off ^ ((off >> 3) & 0x30u);
        CP16(dst + sw, sp);
    }
}

// SW64 chunk (K=32): 3 products x 2 K-steps (proj)
__device__ __forceinline__ void issue_chunk32(uint32_t d, uint32_t ahi, uint32_t alo,
                                              uint32_t bhi, uint32_t blo,
                                              uint32_t idesc, bool first) {
    uint64_t AH = smem_desc64(ahi), AL = smem_desc64(alo);
    uint64_t BH = smem_desc64(bhi), BL = smem_desc64(blo);
#pragma unroll
    for (int ks = 0; ks < 2; ks++) mma_bf16_ss(d, AH + 2 * ks, BH + 2 * ks, idesc, (first && ks == 0) ? 0u : 1u);
#pragma unroll
    for (int ks = 0; ks < 2; ks++) mma_bf16_ss(d, AH + 2 * ks, BL + 2 * ks, idesc, 1u);
#pragma unroll
    for (int ks = 0; ks < 2; ks++) mma_bf16_ss(d, AL + 2 * ks, BH + 2 * ks, idesc, 1u);
}

// SW64 chunk (K=32): 2 products (A plain bf16, B split) — av
__device__ __forceinline__ void issue_av32(uint32_t d, uint32_t a,
                                           uint32_t bhi, uint32_t blo,
                                           uint32_t idesc, bool first) {
    uint64_t A = smem_desc64(a);
    uint64_t BH = smem_desc64(bhi), BL = smem_desc64(blo);
#pragma unroll
    for (int ks = 0; ks < 2; ks++) mma_bf16_ss(d, A + 2 * ks, BH + 2 * ks, idesc, (first && ks == 0) ? 0u : 1u);
#pragma unroll
    for (int ks = 0; ks < 2; ks++) mma_bf16_ss(d, A + 2 * ks, BL + 2 * ks, idesc, 1u);
}

// SW128 chunk (K=64): 3 products x 4 K-steps, N=256 (qks shot)
__device__ __forceinline__ void issue_chunk(uint32_t d, uint32_t ahi, uint32_t alo,
                                            uint32_t bhi, uint32_t blo,
                                            uint32_t idesc, bool first) {
    uint64_t AH = smem_desc(ahi), AL = smem_desc(alo);
    uint64_t BH = smem_desc(bhi), BL = smem_desc(blo);
#pragma unroll
    for (int ks = 0; ks < 4; ks++) mma_bf16_ss(d, AH + 2 * ks, BH + 2 * ks, idesc, (first && ks == 0) ? 0u : 1u);
#pragma unroll
    for (int ks = 0; ks < 4; ks++) mma_bf16_ss(d, AH + 2 * ks, BL + 2 * ks, idesc, 1u);
#pragma unroll
    for (int ks = 0; ks < 4; ks++) mma_bf16_ss(d, AL + 2 * ks, BH + 2 * ks, idesc, 1u);
}
#endif  // USE_TCGEN05

// ---------------- prep: fused spectral norm + x transpose --------------------
// grid (32, 16, 33), block (32, 8).
// z < 32: transpose tile (b=z, c0=y*32, n0=x*32). z == 32: sn (x<3, y==0).
__global__ void prep_kernel(const float* __restrict__ x,
                            const float* __restrict__ Wq, const float* __restrict__ uq, const float* __restrict__ bq,
                            const float* __restrict__ Wk, const float* __restrict__ uk, const float* __restrict__ bk,
                            const float* __restrict__ Wv, const float* __restrict__ uv, const float* __restrict__ bv) {
    if (blockIdx.z == 32) {
        if (blockIdx.y != 0 || blockIdx.x >= 3) return;
        const float* W; const float* u; const float* bias; int out; int dst;
        if (blockIdx.x == 0)      { W = Wq; u = uq; bias = bq; out = CQ;   dst = 0;   }
        else if (blockIdx.x == 1) { W = Wk; u = uk; bias = bk; out = CQ;   dst = 64;  }
        else                      { W = Wv; u = uv; bias = bv; out = C_IN; dst = 128; }

        __shared__ float su[C_IN];
        __shared__ float sv[C_IN];
        __shared__ float red[256];
        int tid = threadIdx.y * 32 + threadIdx.x;

        for (int i = tid; i < out; i += 256) { su[i] = u[i]; g_bias[dst + i] = bias[i]; }
        __syncthreads();

        float t0 = 0.f, t1 = 0.f;
        for (int i = 0; i < out; i++) {
            t0 += W[i * C_IN + tid] * su[i];
            t1 += W[i * C_IN + tid + 256] * su[i];
        }
        red[tid] = t0 * t0 + t1 * t1;
        __syncthreads();
        for (int s = 128; s > 0; s >>= 1) { if (tid < s) red[tid] += red[tid + s]; __syncthreads(); }
        float nv = sqrtf(red[0]);
        sv[tid] = t0 / nv;
        sv[tid + 256] = t1 / nv;
        __syncthreads();

        float p = 0.f;
        for (int i = tid; i < out; i += 256) {
            float r = 0.f;
            for (int j = 0; j < C_IN; j++) r += W[i * C_IN + j] * sv[j];
            p += r * r;
        }
        red[tid] = p;
        __syncthreads();
        for (int s = 128; s > 0; s >>= 1) { if (tid < s) red[tid] += red[tid + s]; __syncthreads(); }
        float inv_sigma = rsqrtf(red[0]);

        for (int e = tid; e < out * C_IN; e += 256) {
            float val = W[e] * inv_sigma;
            __nv_bfloat16 h, l;
            split1(val, h, l);
            g_Wn_hi[(size_t)dst * C_IN + e] = h;
            g_Wn_lo[(size_t)dst * C_IN + e] = l;
        }
        return;
    }

    __shared__ float t[32][33];
    int b = blockIdx.z, c0 = blockIdx.y * 32, n0 = blockIdx.x * 32;
    int tx = threadIdx.x, ty = threadIdx.y;
    const float* src = x + (size_t)b * C_IN * N_TOK;
    size_t dbase = (size_t)b * N_TOK * C_IN;
#pragma unroll
    for (int i = ty; i < 32; i += 8) t[i][tx] = src[(size_t)(c0 + i) * N_TOK + n0 + tx];
    __syncthreads();
#pragma unroll
    for (int i = ty; i < 32; i += 8) {
        float val = t[tx][i];
        __nv_bfloat16 h, l;
        split1(val, h, l);
        size_t off = dbase + (size_t)(n0 + i) * C_IN + c0 + tx;
        g_xT_hi[off] = h;
        g_xT_lo[off] = l;
    }
}

// ---------------- proj: D[n=128][o 256-tile], 2-buffer, 2 CTAs/SM -----------
// grid (8, 3, BATCH): n0 = x*128, o0 = y*256, NN = (y<2)?256:128
__global__ void __launch_bounds__(256, 2) proj_mma() {
#if USE_TCGEN05
    extern __shared__ char dyn[];
    __shared__ uint32_t s_tmem;
    __shared__ uint64_t s_mb[2];
    __shared__ float s_bias[256];

    int tid = threadIdx.x, wid = tid >> 5, lane = tid & 31;
    int b = blockIdx.z, n0 = blockIdx.x * 128, y = blockIdx.y;
    int o0 = y * 256;
    int NN = (y < 2) ? 256 : 128;
    uint32_t idesc = IDESC(NN);

    uint32_t dynb = (cvta_smem(dyn) + 1023u) & ~1023u;
    uint32_t mb0 = cvta_smem(&s_mb[0]), mb1 = cvta_smem(&s_mb[1]);

    if (wid == 0) { TC_ALLOC(cvta_smem(&s_tmem), 256); TC_RELINQ(); }
    if (tid == 0) { MB_INIT(mb0, 1); MB_INIT(mb1, 1); }
    for (int i = tid; i < NN; i += 256) s_bias[i] = g_bias[o0 + i];
    __syncthreads();
    uint32_t tmem = s_tmem;

    const __nv_bfloat16* Ah = g_xT_hi + ((size_t)b * N_TOK + n0) * C_IN;
    const __nv_bfloat16* Al = g_xT_lo + ((size_t)b * N_TOK + n0) * C_IN;
    const __nv_bfloat16* Bh = g_Wn_hi + (size_t)o0 * C_IN;
    const __nv_bfloat16* Bl = g_Wn_lo + (size_t)o0 * C_IN;

    int ph0 = 0, ph1 = 0;
    const int KT = C_IN / 32;   // 16
    for (int kt = 0; kt < KT; kt++) {
        int p = kt & 1;
        if (kt >= 2) {
            if (p == 0) { MB_WAIT(mb0, ph0); ph0 ^= 1; }
            else        { MB_WAIT(mb1, ph1); ph1 ^= 1; }
        }
        uint32_t base = dynb + (uint32_t)p * 49152u;
        int k0 = kt * 32;
        copy_rows64(Ah, C_IN, k0, base, 128, tid);
        copy_rows64(Al, C_IN, k0, base + 8192u, 128, tid);
        copy_rows64(Bh, C_IN, k0, base + 16384u, NN, tid);
        copy_rows64(Bl, C_IN, k0, base + 32768u, NN, tid);
        CP_COMMIT();
        CP_WAIT0();
        __syncthreads();
        if (wid == 0 && elect_one()) {
            FENCE_ASYNC();
            issue_chunk32(tmem, base, base + 8192u, base + 16384u, base + 32768u, idesc, kt == 0);
            TC_COMMIT(p == 0 ? mb0 : mb1);
        }
    }
    MB_WAIT(mb0, ph0);
    MB_WAIT(mb1, ph1);
    TC_FENCE_AFTER();
    __syncthreads();

    float* tb = (float*)dyn;   // reuse pipeline buffers for transpose staging
    for (int c0 = 0; c0 < NN; c0 += 32) {
        int oc0 = o0 + c0;
        bool dir = oc0 < 128;
        if (tid < 128) {
            uint32_t r[32];
            LDTM32(r, tmem + c0);
            TC_WAIT_LD();
            if (dir) {
                int n = n0 + wid * 32 + lane;
                int oo = (oc0 < 64) ? oc0 : (oc0 - 64);
                uint32_t* hi = (uint32_t*)((oc0 < 64) ? g_qT_hi : g_kT_hi) + ((size_t)b * N_TOK + n) * 32;
                uint32_t* lo = (uint32_t*)((oc0 < 64) ? g_qT_lo : g_kT_lo) + ((size_t)b * N_TOK + n) * 32;
#pragma unroll
                for (int j = 0; j < 32; j += 4) {
                    uint32_t h0, l0, h1, l1;
                    pack_split2(__uint_as_float(r[j + 0]) + s_bias[c0 + j + 0],
                                __uint_as_float(r[j + 1]) + s_bias[c0 + j + 1], h0, l0);
                    pack_split2(__uint_as_float(r[j + 2]) + s_bias[c0 + j + 2],
                                __uint_as_float(r[j + 3]) + s_bias[c0 + j + 3], h1, l1);
                    *(uint2*)(hi + ((oo + j) >> 1)) = make_uint2(h0, h1);
                    *(uint2*)(lo + ((oo + j) >> 1)) = make_uint2(l0, l1);
                }
            } else {
                int cb = wid * 1056 + lane * 33;
#pragma unroll
                for (int j = 0; j < 32; j++) tb[cb + j] = __uint_as_float(r[j]);
            }
        }
        if (!dir) {
            __syncthreads();
            int cg = oc0 - 128;
#pragma unroll
            for (int i = 0; i < 16; i++) {
                int rid = wid * 16 + i;
                int wsrc = rid >> 5, j = rid & 31;
                float val = tb[wsrc * 1056 + lane * 33 + j] + s_bias[c0 + j];
                __nv_bfloat16 h, l;
                split1(val, h, l);
                size_t off = ((size_t)b * C_IN + cg + j) * N_TOK + n0 + wsrc * 32 + lane;
                g_v_hi[off] = h;
                g_v_lo[off] = l;
            }
            __syncthreads();
        }
    }
    __syncthreads();
    if (wid == 0) TC_DEALLOC(tmem, 256);
#else
    int tid = threadIdx.x;
    int b = blockIdx.z, n0 = blockIdx.x * 128, y = blockIdx.y, o0 = y * 256;
    int NN = (y < 2) ? 256 : 128;
    for (int e = tid; e < 128 * NN; e += 256) {
        int n = n0 + (e & 127);
        int oc = o0 + (e >> 7);
        const __nv_bfloat16* xh = g_xT_hi + ((size_t)b * N_TOK + n) * C_IN;
        const __nv_bfloat16* xl = g_xT_lo + ((size_t)b * N_TOK + n) * C_IN;
        const __nv_bfloat16* wh = g_Wn_hi + (size_t)oc * C_IN;
        const __nv_bfloat16* wl = g_Wn_lo + (size_t)oc * C_IN;
        float s = 0.f;
        for (int c = 0; c < C_IN; c++) {
            float xa = __bfloat162float(xh[c]) + __bfloat162float(xl[c]);
            float wa = __bfloat162float(wh[c]) + __bfloat162float(wl[c]);
            s += xa * wa;
        }
        s += g_bias[oc];
        __nv_bfloat16 h, l;
        split1(s, h, l);
        if (oc < 64)       { size_t o = ((size_t)b * N_TOK + n) * CQ + oc;        g_qT_hi[o] = h; g_qT_lo[o] = l; }
        else if (oc < 128) { size_t o = ((size_t)b * N_TOK + n) * CQ + (oc - 64); g_kT_hi[o] = h; g_kT_lo[o] = l; }
        else               { size_t o = ((size_t)b * C_IN + (oc - 128)) * N_TOK + n; g_v_hi[o] = h; g_v_lo[o] = l; }
    }
#endif
}

// ---------------- qks: fused QK^T + exp + row-sum, quarter-tiled -------------
// grid (8, BATCH): m0 = x*128. Four N=256 shots (TMEM 256 cols, 2 CTAs/SM).
// smem: A hi 16K | A lo 16K | B hi 32K | B lo 32K = 96KB
__global__ void __launch_bounds__(256, 2) qks_mma() {
#if USE_TCGEN05
    extern __shared__ char dyn[];
    __shared__ uint32_t s_tmem;
    __shared__ uint64_t s_mb[2];

    int tid = threadIdx.x, wid = tid >> 5, lane = tid & 31;
    int b = blockIdx.y, m0 = blockIdx.x * 128;
    uint32_t idesc = IDESC(256);

    uint32_t dynb = (cvta_smem(dyn) + 1023u) & ~1023u;
    uint32_t AHI = dynb, ALO = dynb + 16384u, BHI = dynb + 32768u, BLO = dynb + 65536u;
    uint32_t mba[2];
    mba[0] = cvta_smem(&s_mb[0]);
    mba[1] = cvta_smem(&s_mb[1]);

    if (wid == 0) { TC_ALLOC(cvta_smem(&s_tmem), 256); TC_RELINQ(); }
    if (tid == 0) { MB_INIT(mba[0], 1); MB_INIT(mba[1], 1); }
    __syncthreads();
    uint32_t tmem = s_tmem;

    const __nv_bfloat16* Kh = g_kT_hi + ((size_t)b * N_TOK + m0) * CQ;
    const __nv_bfloat16* Kl = g_kT_lo + ((size_t)b * N_TOK + m0) * CQ;
    const __nv_bfloat16* Qh = g_qT_hi + (size_t)b * N_TOK * CQ;
    const __nv_bfloat16* Ql = g_qT_lo + (size_t)b * N_TOK * CQ;

    // A + B shot0
    copy_rows(Kh, CQ, 0, AHI, 128, tid);
    copy_rows(Kl, CQ, 0, ALO, 128, tid);
    copy_rows(Qh, CQ, 0, BHI, 256, tid);
    copy_rows(Ql, CQ, 0, BLO, 256, tid);
    CP_COMMIT();
    CP_WAIT0();
    __syncthreads();
    if (wid == 0 && elect_one()) {
        FENCE_ASYNC();
        issue_chunk(tmem, AHI, ALO, BHI, BLO, idesc, true);
        TC_COMMIT(mba[0]);
    }

    float rsum = 0.f;
    int m = m0 + wid * 32 + lane;
    uint32_t* Ph = (uint32_t*)g_P + ((size_t)b * N_TOK + m) * 512;

    for (int shot = 0; shot < 4; shot++) {
        MB_WAIT(mba[shot & 1], (shot >> 1) & 1);
        TC_FENCE_AFTER();
        if (shot < 3) {   // B buffer consumed by completed MMA: prefetch next quarter
            copy_rows(Qh + (size_t)(shot + 1) * 256 * CQ, CQ, 0, BHI, 256, tid);
            copy_rows(Ql + (size_t)(shot + 1) * 256 * CQ, CQ, 0, BLO, 256, tid);
            CP_COMMIT();
        }
        if (tid < 128) {
            for (int c0 = 0; c0 < 256; c0 += 32) {
                uint32_t r[32];
                LDTM32(r, tmem + c0);
                TC_WAIT_LD();
                uint32_t hb[16];
#pragma unroll
                for (int j = 0; j < 32; j += 2) {
                    float e0 = __expf(__uint_as_float(r[j]));
                    float e1 = __expf(__uint_as_float(r[j + 1]));
                    rsum += e0 + e1;
                    hb[j >> 1] = pack_bf2(e0, e1);
                }
                int base = shot * 128 + (c0 >> 1);
#pragma unroll
                for (int q = 0; q < 4; q++)
                    *(uint4*)(Ph + base + q * 4) = make_uint4(hb[q*4], hb[q*4+1], hb[q*4+2], hb[q*4+3]);
            }
        }
        if (shot < 3) {
            TC_FENCE_BEFORE();
            CP_WAIT0();
            __syncthreads();
            if (wid == 0 && elect_one()) {
                FENCE_ASYNC();
                TC_FENCE_AFTER();
                issue_chunk(tmem, AHI, ALO, BHI, BLO, idesc, true);
                TC_COMMIT(mba[(shot + 1) & 1]);
            }
        }
    }
    if (tid < 128) g_rsum[(size_t)b * N_TOK + m] = rsum;
    __syncthreads();
    if (wid == 0) TC_DEALLOC(tmem, 256);
#else
    int tid = threadIdx.x;
    int b = blockIdx.y, m0 = blockIdx.x * 128;
    if (tid < 128) {
        int m = m0 + tid;
        const __nv_bfloat16* kh = g_kT_hi + ((size_t)b * N_TOK + m) * CQ;
        const __nv_bfloat16* kl = g_kT_lo + ((size_t)b * N_TOK + m) * CQ;
        float rsum = 0.f;
        for (int n = 0; n < N_TOK; n++) {
            const __nv_bfloat16* qh = g_qT_hi + ((size_t)b * N_TOK + n) * CQ;
            const __nv_bfloat16* ql = g_qT_lo + ((size_t)b * N_TOK + n) * CQ;
            float s = 0.f;
            for (int o = 0; o < CQ; o++)
                s += (__bfloat162float(qh[o]) + __bfloat162float(ql[o])) *
                     (__bfloat162float(kh[o]) + __bfloat162float(kl[o]));
            float e = __expf(s);
            rsum += e;
            g_P[((size_t)b * N_TOK + m) * N_TOK + n] = __float2bfloat16(e);
        }
        g_rsum[(size_t)b * N_TOK + m] = rsum;
    }
#endif
}

// ---------------- av: D[m=128][c=256], 2-buffer, 2 CTAs/SM ------------------
// grid (8, 2, BATCH): m0 = x*128, c0g = y*256. A = bf16 P (no split), B = v hi/lo.
__global__ void __launch_bounds__(256, 2) av_mma(const float* __restrict__ x,
                                                 const float* __restrict__ gamma_p,
                                                 float* __restrict__ out) {
#if USE_TCGEN05
    extern __shared__ char dyn[];
    __shared__ uint32_t s_tmem;
    __shared__ uint64_t s_mb[2];

    int tid = threadIdx.x, wid = tid >> 5, lane = tid & 31;
    int b = blockIdx.z, m0 = blockIdx.x * 128, c0g = blockIdx.y * 256;
    uint32_t idesc = IDESC(256);

    uint32_t dynb = (cvta_smem(dyn) + 1023u) & ~1023u;
    uint32_t mb0 = cvta_smem(&s_mb[0]), mb1 = cvta_smem(&s_mb[1]);

    if (wid == 0) { TC_ALLOC(cvta_smem(&s_tmem), 256); TC_RELINQ(); }
    if (tid == 0) { MB_INIT(mb0, 1); MB_INIT(mb1, 1); }
    __syncthreads();
    uint32_t tmem = s_tmem;

    const __nv_bfloat16* Ap = g_P    + ((size_t)b * N_TOK + m0) * N_TOK;
    const __nv_bfloat16* Bh = g_v_hi + ((size_t)b * C_IN + c0g) * N_TOK;
    const __nv_bfloat16* Bl = g_v_lo + ((size_t)b * C_IN + c0g) * N_TOK;

    int ph0 = 0, ph1 = 0;
    const int KT = N_TOK / 32;   // 32
    for (int kt = 0; kt < KT; kt++) {
        int p = kt & 1;
        if (kt >= 2) {
            if (p == 0) { MB_WAIT(mb0, ph0); ph0 ^= 1; }
            else        { MB_WAIT(mb1, ph1); ph1 ^= 1; }
        }
        uint32_t base = dynb + (uint32_t)p * 40960u;
        int k0 = kt * 32;
        copy_rows64(Ap, N_TOK, k0, base, 128, tid);
        copy_rows64(Bh, N_TOK, k0, base + 8192u, 256, tid);
        copy_rows64(Bl, N_TOK, k0, base + 24576u, 256, tid);
        CP_COMMIT();
        CP_WAIT0();
        __syncthreads();
        if (wid == 0 && elect_one()) {
            FENCE_ASYNC();
            issue_av32(tmem, base, base + 8192u, base + 24576u, idesc, kt == 0);
            TC_COMMIT(p == 0 ? mb0 : mb1);
        }
    }
    MB_WAIT(mb0, ph0);
    MB_WAIT(mb1, ph1);
    TC_FENCE_AFTER();

    float g = *gamma_p;
    int m = m0 + wid * 32 + lane;
    float ginv = (tid < 128) ? (g / g_rsum[(size_t)b * N_TOK + m]) : 0.f;
    for (int c0 = 0; c0 < 256; c0 += 32) {
        if (tid < 128) {
            uint32_t r[32];
            LDTM32(r, tmem + c0);
            TC_WAIT_LD();
#pragma unroll
            for (int j = 0; j < 32; j++) {
                int c = c0g + c0 + j;
                size_t off = ((size_t)b * C_IN + c) * N_TOK + m;
                out[off] = ginv * __uint_as_float(r[j]) + x[off];
            }
        }
    }
    __syncthreads();
    if (wid == 0) TC_DEALLOC(tmem, 256);
#else
    int tid = threadIdx.x;
    int b = blockIdx.z, m0 = blockIdx.x * 128, c0g = blockIdx.y * 256;
    float g = *gamma_p;
    for (int e = tid; e < 128 * 256; e += 256) {
        int m = m0 + (e & 127);
        int c = c0g + (e >> 7);
        const __nv_bfloat16* vh = g_v_hi + ((size_t)b * C_IN + c) * N_TOK;
        const __nv_bfloat16* vl = g_v_lo + ((size_t)b * C_IN + c) * N_TOK;
        const __nv_bfloat16* pp = g_P + ((size_t)b * N_TOK + m) * N_TOK;
        float s = 0.f;
        for (int n = 0; n < N_TOK; n++)
            s += (__bfloat162float(vh[n]) + __bfloat162float(vl[n])) * __bfloat162float(pp[n]);
        size_t off = ((size_t)b * C_IN + c) * N_TOK + m;
        out[off] = g * s / g_rsum[(size_t)b * N_TOK + m] + x[off];
    }
#endif
}

// ---------------- launch -----------------------------------------------------
extern "C" void kernel_launch(void* const* d_in, const int* in_sizes, int n_in,
                              void* d_out, int out_size) {
    const float* x     = (const float*)d_in[0];
    const float* Wq    = (const float*)d_in[1];
    const float* bq    = (const float*)d_in[2];
    const float* uq    = (const float*)d_in[3];
    const float* Wk    = (const float*)d_in[4];
    const float* bk    = (const float*)d_in[5];
    const float* uk    = (const float*)d_in[6];
    const float* Wv    = (const float*)d_in[7];
    const float* bv    = (const float*)d_in[8];
    const float* uv    = (const float*)d_in[9];
    const float* gamma = (const float*)d_in[10];
    float* out = (float*)d_out;

    cudaFuncSetAttribute(proj_mma, cudaFuncAttributeMaxDynamicSharedMemorySize, 99328);
    cudaFuncSetAttribute(qks_mma,  cudaFuncAttributeMaxDynamicSharedMemorySize, 99328);
    cudaFuncSetAttribute(av_mma,   cudaFuncAttributeMaxDynamicSharedMemorySize, 82944);

    prep_kernel<<<dim3(32, 16, 33), dim3(32, 8)>>>(x, Wq, uq, bq, Wk, uk, bk, Wv, uv, bv);
    proj_mma<<<dim3(8, 3, BATCH), 256, 99328>>>();
    qks_mma<<<dim3(8, BATCH), 256, 99328>>>();
    av_mma<<<dim3(8, 2, BATCH), 256, 82944>>>(x, gamma, out);
}